// round 13
// baseline (speedup 1.0000x reference)
#include <cuda_runtime.h>
#include <cuda_bf16.h>
#include <cstdint>
#include <cstddef>

#define SEQ_LEN 16384
#define HID 2048
#define EMBD 512
#define NCH 128
#define ZD 2560
#define SMEM_ROWS 52
#define LSTM_SMEM (SMEM_ROWS * 4096 + HID * 4 + 64 * 4)   // 221,440 B
#define PGEMM_SMEM ((64 + 128) * 129 * 4)                  // 99,072 B

__device__ __nv_bfloat16 g_Wh[(size_t)4 * HID * HID];      // [gate][row][k], k over h-part
__device__ float         g_P[(size_t)NCH * 4 * HID];       // x-part preact + bias
__device__ float         g_H[((size_t)SEQ_LEN + 1) * HID]; // h history
__device__ unsigned int  g_ctr;

__device__ __forceinline__ float bflo(unsigned int w) { return __uint_as_float(w << 16); }
__device__ __forceinline__ float bfhi(unsigned int w) { return __uint_as_float(w & 0xffff0000u); }
__device__ __forceinline__ float sigmoid_f(float x) { return 1.0f / (1.0f + __expf(-x)); }
__device__ __forceinline__ float tanh_f(float x)    { return 2.0f / (1.0f + __expf(-2.0f * x)) - 1.0f; }

__global__ void init_ctr() { g_ctr = 0u; }

// ---- convert recurrent halves of Wf/Wi/Wg/Wo to bf16 ----
__global__ void __launch_bounds__(256) wh_convert(
    const float* __restrict__ Wf, const float* __restrict__ Wi,
    const float* __restrict__ Wg, const float* __restrict__ Wo)
{
    size_t idx = (size_t)blockIdx.x * 256 + threadIdx.x;   // bf16-pair index
    if (idx >= (size_t)4 * HID * HID / 2) return;
    unsigned gate = (unsigned)(idx >> 21);
    unsigned rem  = (unsigned)idx & ((1u << 21) - 1u);
    unsigned row  = rem >> 10;
    unsigned p    = rem & 1023u;
    const float* W = (gate == 0) ? Wf : (gate == 1) ? Wi : (gate == 2) ? Wg : Wo;
    float2 v = *(const float2*)(W + (size_t)row * ZD + EMBD + 2u * p);
    reinterpret_cast<__nv_bfloat162*>(g_Wh)[idx] = __floats2bfloat162_rn(v.x, v.y);
}

// ---- P table: [8192 x 512] @ [512 x 128] exact fp32 ----
__global__ void __launch_bounds__(256) pgemm_kernel(
    const float* __restrict__ Wf, const float* __restrict__ bf,
    const float* __restrict__ Wi, const float* __restrict__ bi,
    const float* __restrict__ Wg, const float* __restrict__ bg,
    const float* __restrict__ Wo, const float* __restrict__ bo,
    const float* __restrict__ emb)
{
    extern __shared__ float psm[];
    float* sW = psm;               // [64][129]
    float* sE = psm + 64 * 129;    // [128][129]
    const int tid = threadIdx.x;
    const int ty = tid >> 4, tx = tid & 15;
    const int gpos0 = blockIdx.x * 64;
    const int gate = gpos0 >> 11;
    const int rowbase = gpos0 & (HID - 1);
    const float* W  = (gate == 0) ? Wf : (gate == 1) ? Wi : (gate == 2) ? Wg : Wo;
    const float* bb = (gate == 0) ? bf : (gate == 1) ? bi : (gate == 2) ? bg : bo;

    float acc[4][8];
#pragma unroll
    for (int i = 0; i < 4; i++)
#pragma unroll
        for (int j = 0; j < 8; j++) acc[i][j] = 0.0f;

    for (int kb = 0; kb < 4; kb++) {
        __syncthreads();
        for (int i = tid; i < 64 * 128; i += 256) {
            int r = i >> 7, k = i & 127;
            sW[r * 129 + k] = W[(size_t)(rowbase + r) * ZD + kb * 128 + k];
        }
        for (int i = tid; i < 128 * 128; i += 256) {
            int c = i >> 7, k = i & 127;
            sE[c * 129 + k] = emb[(size_t)c * EMBD + kb * 128 + k];
        }
        __syncthreads();
        for (int k = 0; k < 128; k++) {
            float wv[4], ev[8];
#pragma unroll
            for (int i = 0; i < 4; i++) wv[i] = sW[(ty + 16 * i) * 129 + k];
#pragma unroll
            for (int j = 0; j < 8; j++) ev[j] = sE[(tx + 16 * j) * 129 + k];
#pragma unroll
            for (int i = 0; i < 4; i++)
#pragma unroll
                for (int j = 0; j < 8; j++) acc[i][j] = fmaf(wv[i], ev[j], acc[i][j]);
        }
    }
#pragma unroll
    for (int i = 0; i < 4; i++) {
        float bv = bb[rowbase + ty + 16 * i];
#pragma unroll
        for (int j = 0; j < 8; j++)
            g_P[(size_t)(tx + 16 * j) * (4 * HID) + gpos0 + ty + 16 * i] = acc[i][j] + bv;
    }
}

// ---- persistent LSTM recurrence ----
__global__ void __launch_bounds__(256, 1) lstm_persist(
    const int* __restrict__ seq, float* __restrict__ dout)
{
    const int nb = gridDim.x, b = blockIdx.x;
    const int qq = HID / nb, rm = HID % nb;
    const int R = qq + (b < rm ? 1 : 0);
    const int rbase = b * qq + (b < rm ? b : rm);
    const int nGR = 4 * R;
    const int nSm = (nGR < SMEM_ROWS) ? nGR : SMEM_ROWS;
    const int tid = threadIdx.x, warp = tid >> 5, lane = tid & 31;

    extern __shared__ unsigned char smraw[];
    uint4* wsm  = (uint4*)smraw;                                   // [SMEM_ROWS][256]
    float* hsm  = (float*)(smraw + SMEM_ROWS * 4096);              // [2048]
    float* gacc = (float*)(smraw + SMEM_ROWS * 4096 + HID * 4);    // [64]

    for (int gr = 0; gr < nSm; gr++) {
        int gate = gr & 3, row = rbase + (gr >> 2);
        const uint4* src = (const uint4*)(g_Wh + ((size_t)gate * HID + row) * HID);
        wsm[gr * 256 + tid] = __ldg(src + tid);
    }
    if (tid < R) g_H[rbase + tid] = 0.0f;
    float cst = 0.0f;

    __syncthreads();
    if (tid == 0) {
        __threadfence();
        atomicAdd(&g_ctr, 1u);
        unsigned v;
        do { asm volatile("ld.acquire.gpu.global.u32 %0, [%1];" : "=r"(v) : "l"(&g_ctr)); } while (v < (unsigned)nb);
    }
    __syncthreads();

    for (int t = 0; t < SEQ_LEN; t++) {
        {   // stage h_t into SMEM (L2-coherent loads)
            const float4* hp = (const float4*)(g_H + (size_t)t * HID);
            float4* hs = (float4*)hsm;
            hs[tid]       = __ldcg(hp + tid);
            hs[tid + 256] = __ldcg(hp + tid + 256);
        }
        int ch = __ldg(seq + t);
        float pf = 0.f, pi = 0.f, pg = 0.f, po = 0.f;
        if (tid < R) {
            const float* Pr = g_P + (size_t)ch * (4 * HID) + rbase + tid;
            pf = __ldg(Pr);           pi = __ldg(Pr + HID);
            pg = __ldg(Pr + 2 * HID); po = __ldg(Pr + 3 * HID);
        }
        __syncthreads();

        float hr[64];
#pragma unroll
        for (int c = 0; c < 8; c++) {
            float4 a = *(const float4*)(hsm + c * 256 + lane * 8);
            float4 d = *(const float4*)(hsm + c * 256 + lane * 8 + 4);
            hr[c * 8 + 0] = a.x; hr[c * 8 + 1] = a.y; hr[c * 8 + 2] = a.z; hr[c * 8 + 3] = a.w;
            hr[c * 8 + 4] = d.x; hr[c * 8 + 5] = d.y; hr[c * 8 + 6] = d.z; hr[c * 8 + 7] = d.w;
        }

        for (int gr = warp; gr < nGR; gr += 8) {
            float a0 = 0.f, a1 = 0.f, a2 = 0.f, a3 = 0.f;
            if (gr < nSm) {
                const uint4* wp = wsm + gr * 256 + lane;
#pragma unroll
                for (int c = 0; c < 8; c++) {
                    uint4 w = wp[c * 32];
                    a0 = fmaf(bflo(w.x), hr[c * 8 + 0], a0);
                    a1 = fmaf(bfhi(w.x), hr[c * 8 + 1], a1);
                    a2 = fmaf(bflo(w.y), hr[c * 8 + 2], a2);
                    a3 = fmaf(bfhi(w.y), hr[c * 8 + 3], a3);
                    a0 = fmaf(bflo(w.z), hr[c * 8 + 4], a0);
                    a1 = fmaf(bfhi(w.z), hr[c * 8 + 5], a1);
                    a2 = fmaf(bflo(w.w), hr[c * 8 + 6], a2);
                    a3 = fmaf(bfhi(w.w), hr[c * 8 + 7], a3);
                }
            } else {
                int gate = gr & 3, row = rbase + (gr >> 2);
                const uint4* wp = (const uint4*)(g_Wh + ((size_t)gate * HID + row) * HID) + lane;
#pragma unroll
                for (int c = 0; c < 8; c++) {
                    uint4 w = __ldg(wp + c * 32);
                    a0 = fmaf(bflo(w.x), hr[c * 8 + 0], a0);
                    a1 = fmaf(bfhi(w.x), hr[c * 8 + 1], a1);
                    a2 = fmaf(bflo(w.y), hr[c * 8 + 2], a2);
                    a3 = fmaf(bfhi(w.y), hr[c * 8 + 3], a3);
                    a0 = fmaf(bflo(w.z), hr[c * 8 + 4], a0);
                    a1 = fmaf(bfhi(w.z), hr[c * 8 + 5], a1);
                    a2 = fmaf(bflo(w.w), hr[c * 8 + 6], a2);
                    a3 = fmaf(bfhi(w.w), hr[c * 8 + 7], a3);
                }
            }
            float s = (a0 + a1) + (a2 + a3);
            s += __shfl_xor_sync(0xffffffffu, s, 16);
            s += __shfl_xor_sync(0xffffffffu, s, 8);
            s += __shfl_xor_sync(0xffffffffu, s, 4);
            s += __shfl_xor_sync(0xffffffffu, s, 2);
            s += __shfl_xor_sync(0xffffffffu, s, 1);
            if (lane == 0) gacc[gr] = s;
        }
        __syncthreads();

        if (tid < R) {
            float fg = sigmoid_f(gacc[4 * tid + 0] + pf);
            float ig = sigmoid_f(gacc[4 * tid + 1] + pi);
            float gg = tanh_f   (gacc[4 * tid + 2] + pg);
            float og = sigmoid_f(gacc[4 * tid + 3] + po);
            cst = fg * cst + ig * gg;
            float hn = og * tanh_f(cst);
            g_H[(size_t)(t + 1) * HID + rbase + tid] = hn;
            if (t == SEQ_LEN - 1) {
                dout[(size_t)SEQ_LEN * NCH + rbase + tid] = hn;
                dout[(size_t)SEQ_LEN * NCH + HID + rbase + tid] = cst;
            }
        }

        __syncthreads();
        if (tid == 0) {
            __threadfence();
            atomicAdd(&g_ctr, 1u);
            unsigned tgt = (unsigned)nb * (unsigned)(t + 2), v;
            do { asm volatile("ld.acquire.gpu.global.u32 %0, [%1];" : "=r"(v) : "l"(&g_ctr)); } while (v < tgt);
        }
        __syncthreads();
    }
}

// ---- FC: out[t][c] = bfc[c] + Wfc[c] . h_{t+1} ----
__global__ void __launch_bounds__(256) fc_kernel(
    const float* __restrict__ Wfc, const float* __restrict__ bfc,
    float* __restrict__ out)
{
    __shared__ float sH[128 * 33];
    __shared__ float sW[128 * 33];
    const int tid = threadIdx.x;
    const int ty = tid >> 4, tx = tid & 15;
    const int tb = blockIdx.x * 128;

    float acc[8][8];
#pragma unroll
    for (int i = 0; i < 8; i++)
#pragma unroll
        for (int j = 0; j < 8; j++) acc[i][j] = 0.0f;

    for (int kb = 0; kb < 64; kb++) {
        __syncthreads();
        for (int i = tid; i < 128 * 32; i += 256) {
            int r = i >> 5, k = i & 31;
            sH[r * 33 + k] = g_H[(size_t)(tb + r + 1) * HID + kb * 32 + k];
            sW[r * 33 + k] = Wfc[(size_t)r * HID + kb * 32 + k];
        }
        __syncthreads();
        for (int k = 0; k < 32; k++) {
            float hv[8], wv[8];
#pragma unroll
            for (int i = 0; i < 8; i++) hv[i] = sH[(ty + 16 * i) * 33 + k];
#pragma unroll
            for (int j = 0; j < 8; j++) wv[j] = sW[(tx + 16 * j) * 33 + k];
#pragma unroll
            for (int i = 0; i < 8; i++)
#pragma unroll
                for (int j = 0; j < 8; j++) acc[i][j] = fmaf(hv[i], wv[j], acc[i][j]);
        }
    }
#pragma unroll
    for (int i = 0; i < 8; i++)
#pragma unroll
        for (int j = 0; j < 8; j++)
            out[(size_t)(tb + ty + 16 * i) * NCH + tx + 16 * j] = acc[i][j] + bfc[tx + 16 * j];
}

extern "C" void kernel_launch(void* const* d_in, const int* in_sizes, int n_in,
                              void* d_out, int out_size)
{
    const int*   seq = (const int*)  d_in[0];
    const float* emb = (const float*)d_in[1];
    const float* Wf  = (const float*)d_in[2];
    const float* bf  = (const float*)d_in[3];
    const float* Wi  = (const float*)d_in[4];
    const float* bi  = (const float*)d_in[5];
    const float* Wg  = (const float*)d_in[6];
    const float* bg  = (const float*)d_in[7];
    const float* Wo  = (const float*)d_in[8];
    const float* bo  = (const float*)d_in[9];
    const float* Wfc = (const float*)d_in[10];
    const float* bfc = (const float*)d_in[11];
    float* out = (float*)d_out;

    cudaFuncSetAttribute(lstm_persist, cudaFuncAttributeMaxDynamicSharedMemorySize, LSTM_SMEM);
    cudaFuncSetAttribute(pgemm_kernel, cudaFuncAttributeMaxDynamicSharedMemorySize, PGEMM_SMEM);

    int dev = 0, nsm = 0;
    cudaGetDevice(&dev);
    cudaDeviceGetAttribute(&nsm, cudaDevAttrMultiProcessorCount, dev);
    if (nsm <= 0 || nsm > 512) nsm = 148;

    init_ctr<<<1, 1>>>();
    wh_convert<<<(int)(((size_t)4 * HID * HID / 2 + 255) / 256), 256>>>(Wf, Wi, Wg, Wo);
    pgemm_kernel<<<128, 256, PGEMM_SMEM>>>(Wf, bf, Wi, bi, Wg, bg, Wo, bo, emb);
    lstm_persist<<<nsm, 256, LSTM_SMEM>>>(seq, out);
    fc_kernel<<<SEQ_LEN / 128, 256>>>(Wfc, bfc, out);
}